// round 3
// baseline (speedup 1.0000x reference)
#include <cuda_runtime.h>
#include <cuda_bf16.h>

#define NN 50000
#define NE 800000
#define D  64

// ---- scratch (no allocations allowed; __device__ globals) ----
static __device__ int   g_is64;             // 1 if edge_index is int64, 0 if int32
static __device__ int   g_cnt[NN];
static __device__ int   g_cursor[NN];
static __device__ float g_dis[NN];
static __device__ int   g_rowstart[NN + 1];
static __device__ int2  g_csr[NE];          // {src, __float_as_int(norm)}
static __device__ float g_h[NN * D];        // post-GEMM features
static __device__ float g_buf[NN * D];      // layer output / next layer input

// ============================================================
// edge_index dtype detection: int64 => all high words zero
// ============================================================

__global__ void k_detect(const int* __restrict__ ei32) {
    int all_zero = 1;
    #pragma unroll
    for (int i = 0; i < 64; i++) {
        if (ei32[2 * i + 1] != 0) { all_zero = 0; break; }
    }
    g_is64 = all_zero;
}

__device__ __forceinline__ int load_idx(const void* ei, int pos, int is64) {
    if (is64) return (int)((const long long*)ei)[pos];
    return ((const int*)ei)[pos];
}

// ============================================================
// Preprocessing: degree, deg_inv_sqrt, CSR-by-dst
// ============================================================

__global__ void k_init(void) {
    int v = blockIdx.x * blockDim.x + threadIdx.x;
    if (v < NN) { g_cnt[v] = 0; g_cursor[v] = 0; }
}

__global__ void k_count(const void* __restrict__ ei) {
    int e = blockIdx.x * blockDim.x + threadIdx.x;
    int is64 = g_is64;
    if (e < NE) {
        int dst = load_idx(ei, NE + e, is64);
        atomicAdd(&g_cnt[dst], 1);
    }
}

__global__ void k_dis(void) {
    int v = blockIdx.x * blockDim.x + threadIdx.x;
    if (v < NN) g_dis[v] = rsqrtf((float)(g_cnt[v] + 1));   // +1 self-loop
}

// Single-block exclusive scan of g_cnt -> g_rowstart (50001 entries)
__global__ void k_scan(void) {
    __shared__ int part[1024];
    const int t = threadIdx.x;
    const int CH = (NN + 1023) / 1024;   // 49
    int lo = t * CH;
    int hi = lo + CH; if (hi > NN) hi = NN; if (lo > NN) lo = NN;
    int s = 0;
    for (int i = lo; i < hi; i++) s += g_cnt[i];
    part[t] = s;
    __syncthreads();
    for (int off = 1; off < 1024; off <<= 1) {
        int v = (t >= off) ? part[t - off] : 0;
        __syncthreads();
        part[t] += v;
        __syncthreads();
    }
    int run = (t == 0) ? 0 : part[t - 1];
    for (int i = lo; i < hi; i++) {
        int c = g_cnt[i];
        g_rowstart[i] = run;
        run += c;
    }
    if (t == 1023) g_rowstart[NN] = run;   // == NE
}

__global__ void k_scatter(const void* __restrict__ ei) {
    int e = blockIdx.x * blockDim.x + threadIdx.x;
    int is64 = g_is64;
    if (e < NE) {
        int s = load_idx(ei, e, is64);
        int d = load_idx(ei, NE + e, is64);
        float norm = g_dis[s] * g_dis[d];
        int pos = g_rowstart[d] + atomicAdd(&g_cursor[d], 1);
        g_csr[pos] = make_int2(s, __float_as_int(norm));
    }
}

// ============================================================
// GEMM: g_h = (relu?)(in) @ W       in: 50000x64, W: 64x64
// block = 128 threads, tile = 32 rows
// ============================================================

#define XS_STRIDE 34   // padded transposed X tile stride (conflict-free float2 reads)

__global__ void __launch_bounds__(128) k_gemm(const float* __restrict__ Xext,
                                              int use_ext,
                                              const float* __restrict__ W,
                                              int relu) {
    __shared__ float Ws[64 * 64];            // W row-major
    __shared__ float XsT[64 * XS_STRIDE];    // X tile transposed: XsT[k*34 + row]

    const float* __restrict__ X = use_ext ? Xext : g_buf;
    const int t = threadIdx.x;
    const int rbase = blockIdx.x * 32;

    // load W (4096 floats = 1024 float4, 8 per thread)
    {
        const float4* W4 = (const float4*)W;
        float4* Ws4 = (float4*)Ws;
        #pragma unroll
        for (int i = 0; i < 8; i++) Ws4[t + 128 * i] = W4[t + 128 * i];
    }

    // load X tile transposed: thread t -> row t/4, cols [(t%4)*16, +16)
    {
        int row = t >> 2;
        int cb  = (t & 3) * 16;
        int gr  = rbase + row;
        float4 v0, v1, v2, v3;
        if (gr < NN) {
            const float4* Xr = (const float4*)(X + (size_t)gr * D + cb);
            v0 = Xr[0]; v1 = Xr[1]; v2 = Xr[2]; v3 = Xr[3];
            if (relu) {
                v0.x = fmaxf(v0.x, 0.f); v0.y = fmaxf(v0.y, 0.f); v0.z = fmaxf(v0.z, 0.f); v0.w = fmaxf(v0.w, 0.f);
                v1.x = fmaxf(v1.x, 0.f); v1.y = fmaxf(v1.y, 0.f); v1.z = fmaxf(v1.z, 0.f); v1.w = fmaxf(v1.w, 0.f);
                v2.x = fmaxf(v2.x, 0.f); v2.y = fmaxf(v2.y, 0.f); v2.z = fmaxf(v2.z, 0.f); v2.w = fmaxf(v2.w, 0.f);
                v3.x = fmaxf(v3.x, 0.f); v3.y = fmaxf(v3.y, 0.f); v3.z = fmaxf(v3.z, 0.f); v3.w = fmaxf(v3.w, 0.f);
            }
        } else {
            v0 = v1 = v2 = v3 = make_float4(0.f, 0.f, 0.f, 0.f);
        }
        float* col = XsT + row;
        col[(cb +  0) * XS_STRIDE] = v0.x; col[(cb +  1) * XS_STRIDE] = v0.y;
        col[(cb +  2) * XS_STRIDE] = v0.z; col[(cb +  3) * XS_STRIDE] = v0.w;
        col[(cb +  4) * XS_STRIDE] = v1.x; col[(cb +  5) * XS_STRIDE] = v1.y;
        col[(cb +  6) * XS_STRIDE] = v1.z; col[(cb +  7) * XS_STRIDE] = v1.w;
        col[(cb +  8) * XS_STRIDE] = v2.x; col[(cb +  9) * XS_STRIDE] = v2.y;
        col[(cb + 10) * XS_STRIDE] = v2.z; col[(cb + 11) * XS_STRIDE] = v2.w;
        col[(cb + 12) * XS_STRIDE] = v3.x; col[(cb + 13) * XS_STRIDE] = v3.y;
        col[(cb + 14) * XS_STRIDE] = v3.z; col[(cb + 15) * XS_STRIDE] = v3.w;
    }
    __syncthreads();

    const int cg = t & 7;    // col group: cols [8*cg, 8*cg+8)
    const int rp = t >> 3;   // row pair: rows 2*rp, 2*rp+1

    float acc[16];
    #pragma unroll
    for (int i = 0; i < 16; i++) acc[i] = 0.f;

    #pragma unroll 8
    for (int k = 0; k < 64; k++) {
        float2 x01 = *(const float2*)&XsT[k * XS_STRIDE + 2 * rp];
        float4 wa  = *(const float4*)&Ws[k * 64 + 8 * cg];
        float4 wb  = *(const float4*)&Ws[k * 64 + 8 * cg + 4];
        acc[0]  = fmaf(x01.x, wa.x, acc[0]);  acc[1]  = fmaf(x01.x, wa.y, acc[1]);
        acc[2]  = fmaf(x01.x, wa.z, acc[2]);  acc[3]  = fmaf(x01.x, wa.w, acc[3]);
        acc[4]  = fmaf(x01.x, wb.x, acc[4]);  acc[5]  = fmaf(x01.x, wb.y, acc[5]);
        acc[6]  = fmaf(x01.x, wb.z, acc[6]);  acc[7]  = fmaf(x01.x, wb.w, acc[7]);
        acc[8]  = fmaf(x01.y, wa.x, acc[8]);  acc[9]  = fmaf(x01.y, wa.y, acc[9]);
        acc[10] = fmaf(x01.y, wa.z, acc[10]); acc[11] = fmaf(x01.y, wa.w, acc[11]);
        acc[12] = fmaf(x01.y, wb.x, acc[12]); acc[13] = fmaf(x01.y, wb.y, acc[13]);
        acc[14] = fmaf(x01.y, wb.z, acc[14]); acc[15] = fmaf(x01.y, wb.w, acc[15]);
    }

    int r0 = rbase + 2 * rp;
    if (r0 < NN) {
        float4* o = (float4*)&g_h[(size_t)r0 * D + 8 * cg];
        o[0] = make_float4(acc[0], acc[1], acc[2], acc[3]);
        o[1] = make_float4(acc[4], acc[5], acc[6], acc[7]);
    }
    if (r0 + 1 < NN) {
        float4* o = (float4*)&g_h[(size_t)(r0 + 1) * D + 8 * cg];
        o[0] = make_float4(acc[8],  acc[9],  acc[10], acc[11]);
        o[1] = make_float4(acc[12], acc[13], acc[14], acc[15]);
    }
}

// ============================================================
// Aggregation: out[v] = h[v]*dis[v]^2 + b + sum_{e in row v} h[src_e]*norm_e
// one warp per node, lane owns features [2*lane, 2*lane+1]
// ============================================================

__global__ void __launch_bounds__(256) k_agg(const float* __restrict__ b,
                                             float* __restrict__ dout,
                                             int use_dout) {
    int w = (blockIdx.x * blockDim.x + threadIdx.x) >> 5;
    if (w >= NN) return;
    int lane = threadIdx.x & 31;

    float* __restrict__ out = use_dout ? dout : g_buf;
    const float* __restrict__ H = g_h;

    float2 bb = *(const float2*)&b[2 * lane];
    float2 hv = *(const float2*)&H[(size_t)w * D + 2 * lane];
    float ds  = g_dis[w];
    float d2  = ds * ds;
    float2 acc = make_float2(fmaf(hv.x, d2, bb.x), fmaf(hv.y, d2, bb.y));

    int e  = g_rowstart[w];
    int e1 = g_rowstart[w + 1];

    for (; e + 4 <= e1; e += 4) {
        int2 c0 = g_csr[e + 0];
        int2 c1 = g_csr[e + 1];
        int2 c2 = g_csr[e + 2];
        int2 c3 = g_csr[e + 3];
        float2 h0 = *(const float2*)&H[(size_t)c0.x * D + 2 * lane];
        float2 h1 = *(const float2*)&H[(size_t)c1.x * D + 2 * lane];
        float2 h2 = *(const float2*)&H[(size_t)c2.x * D + 2 * lane];
        float2 h3 = *(const float2*)&H[(size_t)c3.x * D + 2 * lane];
        float n0 = __int_as_float(c0.y);
        float n1 = __int_as_float(c1.y);
        float n2 = __int_as_float(c2.y);
        float n3 = __int_as_float(c3.y);
        acc.x = fmaf(h0.x, n0, acc.x); acc.y = fmaf(h0.y, n0, acc.y);
        acc.x = fmaf(h1.x, n1, acc.x); acc.y = fmaf(h1.y, n1, acc.y);
        acc.x = fmaf(h2.x, n2, acc.x); acc.y = fmaf(h2.y, n2, acc.y);
        acc.x = fmaf(h3.x, n3, acc.x); acc.y = fmaf(h3.y, n3, acc.y);
    }
    for (; e < e1; e++) {
        int2 c = g_csr[e];
        float2 hh = *(const float2*)&H[(size_t)c.x * D + 2 * lane];
        float n = __int_as_float(c.y);
        acc.x = fmaf(hh.x, n, acc.x);
        acc.y = fmaf(hh.y, n, acc.y);
    }

    *(float2*)&out[(size_t)w * D + 2 * lane] = acc;
}

// ============================================================
// Launch
// ============================================================

extern "C" void kernel_launch(void* const* d_in, const int* in_sizes, int n_in,
                              void* d_out, int out_size) {
    const float* x  = (const float*)d_in[0];
    const void*  ei = d_in[1];                 // int32 or int64 [2, 800000], detected on device
    const float* W0 = (const float*)d_in[2];
    const float* b0 = (const float*)d_in[3];
    const float* W1 = (const float*)d_in[4];
    const float* b1 = (const float*)d_in[5];
    const float* W2 = (const float*)d_in[6];
    const float* b2 = (const float*)d_in[7];
    float* out = (float*)d_out;

    // --- preprocessing: dtype sniff, degrees + CSR by dst ---
    k_detect <<<1, 1>>>((const int*)ei);
    k_init   <<<(NN + 255) / 256, 256>>>();
    k_count  <<<(NE + 255) / 256, 256>>>(ei);
    k_dis    <<<(NN + 255) / 256, 256>>>();
    k_scan   <<<1, 1024>>>();
    k_scatter<<<(NE + 255) / 256, 256>>>(ei);

    const int gemm_grid = (NN + 31) / 32;            // 1563
    const int agg_grid  = (NN * 32 + 255) / 256;     // 6250

    // --- layer 0 ---
    k_gemm<<<gemm_grid, 128>>>(x, 1, W0, 0);
    k_agg <<<agg_grid, 256>>>(b0, out, 0);
    // --- layer 1 (relu fused into input read) ---
    k_gemm<<<gemm_grid, 128>>>(x, 0, W1, 1);
    k_agg <<<agg_grid, 256>>>(b1, out, 0);
    // --- layer 2 ---
    k_gemm<<<gemm_grid, 128>>>(x, 0, W2, 1);
    k_agg <<<agg_grid, 256>>>(b2, out, 1);   // write final result to d_out
}